// round 11
// baseline (speedup 1.0000x reference)
#include <cuda_runtime.h>
#include <math.h>
#include <stdint.h>

// PPCA gating layer, GB300 sm_103a — round 11: R10 + barrier-free epilogue.
// x: [B=64, C=256, H=56, W=56] fp32, weight: [HW=3136, 15] fp32.
//
// R10 plateau: DRAM 75.5%, logical throughput already ~87% of spec (replay
// L2 residue). Residual loss = phase lockstep around the two barriers. This
// round removes sync2: after sync1 every warp redundantly computes all 64
// gates (2 per thread: LDS from sgrp + 15-dot + sigmoid, then shuffles to
// assemble each thread's gate4). Warps decouple immediately into their
// store streams. Pass 1 / cp.async staging identical to R10.
//
// CTA = 256 thr = 16 float4-lanes x 16 half-groups (16 ch each), 4 CTAs/SM.

#define BATCH   64
#define CH      256
#define HW      3136
#define HW4     (HW / 4)      // 784 float4 per (b,c) row
#define TILE_S  64
#define LANES   (TILE_S / 4)  // 16 float4 lanes
#define NTHR    256           // 16 lanes x 16 half-groups
#define NREG    8             // channels summed via LDG into registers
#define NSMEM   8             // channels staged via cp.async.cg into smem

#define CP_ASYNC_CG16(dst_u32, src_ptr) \
    asm volatile("cp.async.cg.shared.global [%0], [%1], 16;" \
                 :: "r"(dst_u32), "l"(src_ptr) : "memory")
#define CP_ASYNC_WAIT_ALL() \
    asm volatile("cp.async.wait_all;" ::: "memory")

__global__ __launch_bounds__(NTHR, 4)
void ppca_gate_kernel(const float* __restrict__ x,
                      const float* __restrict__ weight,
                      float* __restrict__ out)
{
    __shared__ float4 sstage[NSMEM * NTHR];   // 32 KB staging (cp.async dst)
    __shared__ float  sgrp[16 * TILE_S];      // half-group sums [16][64]

    const int s0 = blockIdx.x * TILE_S;       // 49 tiles * 64 = 3136
    const int b  = blockIdx.y;

    const int t   = threadIdx.x;
    const int l   = t & 31;                   // lane in warp
    const int sl4 = t & (LANES - 1);          // float4 lane 0..15
    const int h   = t >> 4;                   // half-group 0..15 (16 ch each)

    const size_t base4 = (size_t)b * CH * HW4 + (size_t)(blockIdx.x * LANES) + sl4
                       + (size_t)(h * 16) * HW4;
    const float4* xb4 = reinterpret_cast<const float4*>(x) + base4;

    // ---- Pass 1a: queue 8 cp.async.cg 16B copies (bypass L1/RF) ----
    const uint32_t sbase =
        (uint32_t)__cvta_generic_to_shared(&sstage[t]);
    #pragma unroll
    for (int cc = 0; cc < NSMEM; cc++) {
        CP_ASYNC_CG16(sbase + cc * NTHR * 16,
                      xb4 + (size_t)(NREG + cc) * HW4);
    }

    // ---- Pass 1b: 8 LDG.128 sums while copies are in flight ----
    float4 r[NREG];
    float s0a = 0.f, s1a = 0.f, s2a = 0.f, s3a = 0.f;
    #pragma unroll
    for (int cc = 0; cc < NREG; cc++) {
        r[cc] = __ldg(xb4 + (size_t)cc * HW4);
        s0a += r[cc].x; s1a += r[cc].y; s2a += r[cc].z; s3a += r[cc].w;
    }

    // ---- Pass 1c: drain this thread's copies, finish sums from smem ----
    CP_ASYNC_WAIT_ALL();
    #pragma unroll
    for (int cc = 0; cc < NSMEM; cc++) {
        float4 v = sstage[cc * NTHR + t];
        s0a += v.x; s1a += v.y; s2a += v.z; s3a += v.w;
    }
    reinterpret_cast<float4*>(sgrp)[h * LANES + sl4] =
        make_float4(s0a, s1a, s2a, s3a);
    __syncthreads();   // the ONLY barrier: sgrp complete

    // ---- Gate: every warp computes all 64 gates (2 per thread) ----
    // Thread computes gates for tile positions p0 = l and p1 = l + 32.
    float gres[2];
    #pragma unroll
    for (int pos = 0; pos < 2; pos++) {
        const int p = l + pos * 32;

        float S8[8];
        #pragma unroll
        for (int j = 0; j < 8; j++)
            S8[j] = sgrp[(2*j) * TILE_S + p] + sgrp[(2*j+1) * TILE_S + p];

        float S4[4], S2[2], S1;
        #pragma unroll
        for (int j = 0; j < 4; j++) S4[j] = S8[2*j] + S8[2*j+1];
        S2[0] = S4[0] + S4[1];
        S2[1] = S4[2] + S4[3];
        S1    = S2[0] + S2[1];

        // feats in reference concat order: [scale1, scale2, scale4, scale8]
        float f[15];
        f[0] = S1 * (1.0f / 256.0f);
        f[1] = S2[0] * (1.0f / 128.0f);
        f[2] = S2[1] * (1.0f / 128.0f);
        #pragma unroll
        for (int j = 0; j < 4; j++) f[3 + j] = S4[j] * (1.0f / 64.0f);
        #pragma unroll
        for (int j = 0; j < 8; j++) f[7 + j] = S8[j] * (1.0f / 32.0f);

        float mu = 0.0f;
        #pragma unroll
        for (int j = 0; j < 15; j++) mu += f[j];
        mu *= (1.0f / 15.0f);

        float var = 0.0f;
        #pragma unroll
        for (int j = 0; j < 15; j++) {
            float d = f[j] - mu;
            var += d * d;
        }
        var *= (1.0f / 15.0f);
        const float inv_std = rsqrtf(var);

        const float* wr = weight + (size_t)(s0 + p) * 15;
        float z = 0.0f;
        #pragma unroll
        for (int j = 0; j < 15; j++)
            z += (f[j] - mu) * __ldg(wr + j);
        z *= inv_std;

        gres[pos] = 1.0f / (1.0f + expf(-z));
    }

    // Assemble this thread's gate4 (positions 4*sl4 .. 4*sl4+3) via shuffles.
    float4 gate4;
    {
        float gk[4];
        #pragma unroll
        for (int k = 0; k < 4; k++) {
            const int q   = 4 * sl4 + k;       // tile position 0..63
            const int src = q & 31;
            float va = __shfl_sync(0xFFFFFFFFu, gres[0], src);
            float vb = __shfl_sync(0xFFFFFFFFu, gres[1], src);
            gk[k] = (q < 32) ? va : vb;
        }
        gate4 = make_float4(gk[0], gk[1], gk[2], gk[3]);
    }

    // ---- Pass 2: multiply staged data by gate, stores (no 2nd barrier) ----
    float4* ob4 = reinterpret_cast<float4*>(out) + base4;

    #pragma unroll
    for (int cc = 0; cc < NREG; cc++) {
        float4 v = r[cc];
        v.x *= gate4.x; v.y *= gate4.y; v.z *= gate4.z; v.w *= gate4.w;
        ob4[(size_t)cc * HW4] = v;
    }
    #pragma unroll
    for (int cc = 0; cc < NSMEM; cc++) {
        float4 v = sstage[cc * NTHR + t];
        v.x *= gate4.x; v.y *= gate4.y; v.z *= gate4.z; v.w *= gate4.w;
        ob4[(size_t)(NREG + cc) * HW4] = v;
    }
}

extern "C" void kernel_launch(void* const* d_in, const int* in_sizes, int n_in,
                              void* d_out, int out_size)
{
    const float* x      = (const float*)d_in[0];
    const float* weight = (const float*)d_in[1];
    float* out          = (float*)d_out;

    dim3 grid(HW / TILE_S, BATCH);   // (49, 64)
    ppca_gate_kernel<<<grid, NTHR>>>(x, weight, out);
}

// round 12
// speedup vs baseline: 1.0100x; 1.0100x over previous
#include <cuda_runtime.h>
#include <math.h>
#include <stdint.h>

// PPCA gating layer, GB300 sm_103a — round 12: 2-tile pipelined CTA.
// x: [B=64, C=256, H=56, W=56] fp32, weight: [HW=3136, 15] fp32.
//
// R10 residual: during a CTA's gate+store phase it issues no reads; overlap
// relied on chance decorrelation of co-resident CTAs. This round each CTA
// processes TWO tiles (same spatial tile, batches 2y, 2y+1) and queues
// tile-1's cp.async staging right after tile-0's sync1 — T1's read stream is
// in flight through T0's gate+store phase. Zero redundant compute (R11's
// mistake avoided).
//
// Staging split NREG=10 / NSMEM=6 keeps double-buffered smem at 52.3 KB
// (3 CTAs = 157 KB, L1 carveout ~71 KB — safe per R8 lesson). 24 warps/SM,
// each with a nearly gapless 32-deep (2x16) memory stream.

#define BATCH   64
#define CH      256
#define HW      3136
#define HW4     (HW / 4)      // 784 float4 per (b,c) row
#define TILE_S  64
#define LANES   (TILE_S / 4)  // 16 float4 lanes
#define NTHR    256           // 16 lanes x 16 half-groups
#define NREG    10            // channels summed via LDG into registers
#define NSMEM   6             // channels staged via cp.async.cg into smem

#define CP_ASYNC_CG16(dst_u32, src_ptr) \
    asm volatile("cp.async.cg.shared.global [%0], [%1], 16;" \
                 :: "r"(dst_u32), "l"(src_ptr) : "memory")
#define CP_ASYNC_WAIT_ALL() \
    asm volatile("cp.async.wait_all;" ::: "memory")

// smem layout (floats): stageA[6*256*4] stageB[6*256*4] sgrp[16*64] sgate[64]
#define SM_STAGE_F4   (NSMEM * NTHR)          // float4 count per buffer
#define SM_BYTES      (2 * SM_STAGE_F4 * 16 + 16 * TILE_S * 4 + TILE_S * 4)

__device__ __forceinline__ float gate_compute(const float* __restrict__ sgrp,
                                              const float* __restrict__ weight,
                                              int p, int s0)
{
    float S8[8];
    #pragma unroll
    for (int j = 0; j < 8; j++)
        S8[j] = sgrp[(2*j) * TILE_S + p] + sgrp[(2*j+1) * TILE_S + p];

    float S4[4], S2[2], S1;
    #pragma unroll
    for (int j = 0; j < 4; j++) S4[j] = S8[2*j] + S8[2*j+1];
    S2[0] = S4[0] + S4[1];
    S2[1] = S4[2] + S4[3];
    S1    = S2[0] + S2[1];

    // feats in reference concat order: [scale1, scale2, scale4, scale8]
    float f[15];
    f[0] = S1 * (1.0f / 256.0f);
    f[1] = S2[0] * (1.0f / 128.0f);
    f[2] = S2[1] * (1.0f / 128.0f);
    #pragma unroll
    for (int j = 0; j < 4; j++) f[3 + j] = S4[j] * (1.0f / 64.0f);
    #pragma unroll
    for (int j = 0; j < 8; j++) f[7 + j] = S8[j] * (1.0f / 32.0f);

    float mu = 0.0f;
    #pragma unroll
    for (int j = 0; j < 15; j++) mu += f[j];
    mu *= (1.0f / 15.0f);

    float var = 0.0f;
    #pragma unroll
    for (int j = 0; j < 15; j++) {
        float d = f[j] - mu;
        var += d * d;
    }
    var *= (1.0f / 15.0f);
    const float inv_std = rsqrtf(var);

    const float* wr = weight + (size_t)(s0 + p) * 15;
    float z = 0.0f;
    #pragma unroll
    for (int j = 0; j < 15; j++)
        z += (f[j] - mu) * __ldg(wr + j);
    z *= inv_std;

    return 1.0f / (1.0f + expf(-z));
}

__global__ __launch_bounds__(NTHR, 3)
void ppca_gate_kernel(const float* __restrict__ x,
                      const float* __restrict__ weight,
                      float* __restrict__ out)
{
    extern __shared__ float4 smem4[];
    float4* sA    = smem4;                    // [6*256] staging T0
    float4* sB    = smem4 + SM_STAGE_F4;      // [6*256] staging T1
    float*  sgrp  = (float*)(smem4 + 2 * SM_STAGE_F4);  // [16][64]
    float*  sgate = sgrp + 16 * TILE_S;       // [64]

    const int s0 = blockIdx.x * TILE_S;       // 49 tiles * 64 = 3136
    const int b0 = 2 * blockIdx.y;            // batches 2y, 2y+1
    const int b1 = b0 + 1;

    const int t   = threadIdx.x;
    const int sl4 = t & (LANES - 1);          // float4 lane 0..15
    const int h   = t >> 4;                   // half-group 0..15 (16 ch each)

    const size_t tileoff = (size_t)(blockIdx.x * LANES) + sl4
                         + (size_t)(h * 16) * HW4;
    const float4* xA = reinterpret_cast<const float4*>(x)
                     + (size_t)b0 * CH * HW4 + tileoff;
    const float4* xB = reinterpret_cast<const float4*>(x)
                     + (size_t)b1 * CH * HW4 + tileoff;

    const uint32_t smA = (uint32_t)__cvta_generic_to_shared(&sA[t]);
    const uint32_t smB = (uint32_t)__cvta_generic_to_shared(&sB[t]);

    // ================= Tile 0: pass 1 =================
    #pragma unroll
    for (int cc = 0; cc < NSMEM; cc++)
        CP_ASYNC_CG16(smA + cc * NTHR * 16, xA + (size_t)(NREG + cc) * HW4);

    float4 r[NREG];
    float s0a = 0.f, s1a = 0.f, s2a = 0.f, s3a = 0.f;
    #pragma unroll
    for (int cc = 0; cc < NREG; cc++) {
        r[cc] = __ldg(xA + (size_t)cc * HW4);
        s0a += r[cc].x; s1a += r[cc].y; s2a += r[cc].z; s3a += r[cc].w;
    }
    CP_ASYNC_WAIT_ALL();
    #pragma unroll
    for (int cc = 0; cc < NSMEM; cc++) {
        float4 v = sA[cc * NTHR + t];
        s0a += v.x; s1a += v.y; s2a += v.z; s3a += v.w;
    }
    reinterpret_cast<float4*>(sgrp)[h * LANES + sl4] =
        make_float4(s0a, s1a, s2a, s3a);
    __syncthreads();                                    // sync1: sgrp T0 ready

    // ---- prefetch Tile 1 staging: in flight through T0 gate+stores ----
    #pragma unroll
    for (int cc = 0; cc < NSMEM; cc++)
        CP_ASYNC_CG16(smB + cc * NTHR * 16, xB + (size_t)(NREG + cc) * HW4);

    // ---- gate T0 ----
    if (t < TILE_S)
        sgate[t] = gate_compute(sgrp, weight, t, s0);
    __syncthreads();                                    // sync2: sgate T0 ready

    // ---- stores T0 ----
    {
        const float4 g4 = reinterpret_cast<const float4*>(sgate)[sl4];
        float4* oA = reinterpret_cast<float4*>(out)
                   + (size_t)b0 * CH * HW4 + tileoff;
        #pragma unroll
        for (int cc = 0; cc < NREG; cc++) {
            float4 v = r[cc];
            v.x *= g4.x; v.y *= g4.y; v.z *= g4.z; v.w *= g4.w;
            oA[(size_t)cc * HW4] = v;
        }
        #pragma unroll
        for (int cc = 0; cc < NSMEM; cc++) {
            float4 v = sA[cc * NTHR + t];
            v.x *= g4.x; v.y *= g4.y; v.z *= g4.z; v.w *= g4.w;
            oA[(size_t)(NREG + cc) * HW4] = v;
        }
    }

    // ================= Tile 1: pass 1b/1c =================
    s0a = 0.f; s1a = 0.f; s2a = 0.f; s3a = 0.f;
    #pragma unroll
    for (int cc = 0; cc < NREG; cc++) {
        r[cc] = __ldg(xB + (size_t)cc * HW4);
        s0a += r[cc].x; s1a += r[cc].y; s2a += r[cc].z; s3a += r[cc].w;
    }
    CP_ASYNC_WAIT_ALL();                                // drains T1 copies
    #pragma unroll
    for (int cc = 0; cc < NSMEM; cc++) {
        float4 v = sB[cc * NTHR + t];
        s0a += v.x; s1a += v.y; s2a += v.z; s3a += v.w;
    }
    // sgrp T0 was only read in gate phase (pre-sync2); safe to overwrite now.
    reinterpret_cast<float4*>(sgrp)[h * LANES + sl4] =
        make_float4(s0a, s1a, s2a, s3a);
    __syncthreads();                                    // sync3: sgrp T1 ready

    if (t < TILE_S)
        sgate[t] = gate_compute(sgrp, weight, t, s0);
    __syncthreads();                                    // sync4: sgate T1 ready

    {
        const float4 g4 = reinterpret_cast<const float4*>(sgate)[sl4];
        float4* oB = reinterpret_cast<float4*>(out)
                   + (size_t)b1 * CH * HW4 + tileoff;
        #pragma unroll
        for (int cc = 0; cc < NREG; cc++) {
            float4 v = r[cc];
            v.x *= g4.x; v.y *= g4.y; v.z *= g4.z; v.w *= g4.w;
            oB[(size_t)cc * HW4] = v;
        }
        #pragma unroll
        for (int cc = 0; cc < NSMEM; cc++) {
            float4 v = sB[cc * NTHR + t];
            v.x *= g4.x; v.y *= g4.y; v.z *= g4.z; v.w *= g4.w;
            oB[(size_t)(NREG + cc) * HW4] = v;
        }
    }
}

extern "C" void kernel_launch(void* const* d_in, const int* in_sizes, int n_in,
                              void* d_out, int out_size)
{
    const float* x      = (const float*)d_in[0];
    const float* weight = (const float*)d_in[1];
    float* out          = (float*)d_out;

    cudaFuncSetAttribute(ppca_gate_kernel,
                         cudaFuncAttributeMaxDynamicSharedMemorySize, SM_BYTES);

    dim3 grid(HW / TILE_S, BATCH / 2);   // (49, 32), 2 batches per CTA
    ppca_gate_kernel<<<grid, NTHR, SM_BYTES>>>(x, weight, out);
}